// round 7
// baseline (speedup 1.0000x reference)
#include <cuda_runtime.h>
#include <math.h>
#include <stdint.h>

#define NTOK 8192
#define DIM  768
#define KCB  8192
#define NHEAD 8
#define DH   96
#define SEQ  512
#define BATCH 16
#define NLAYER 6
#define FFD  2048
#define NEGF (-1e9f)

// ---------------- scratch (device globals: allocation-free contract) -------
__device__ float g_ze[(size_t)NTOK * DIM];
__device__ float g_xnorm[NTOK];
__device__ int   g_pad[NTOK];
__device__ float g_cnorm[KCB];
__device__ float g_big[(size_t)NTOK * KCB];     // VQ distances, then attn scores
__device__ float g_topd[NTOK * 10];
__device__ int   g_topi[NTOK * 10];
__device__ float g_gum[NTOK * 10];
__device__ float g_h[(size_t)NTOK * DIM];
__device__ float g_qkv[(size_t)NTOK * 3 * DIM];
__device__ float g_attn[(size_t)NTOK * DIM];
__device__ float g_tmp[(size_t)NTOK * DIM];
__device__ float g_ffb[(size_t)NTOK * FFD];

// pure fp32 (reference is fp32 — established round 2 vs 5 invariance)
__device__ __forceinline__ float cvt_in(float x) { return x; }

// ---------------- row sumsq (+ optional pad mask and masked copy) ----------
__global__ void rownorm_kernel(const float* __restrict__ src, int ncols,
                               float* __restrict__ norm_out,
                               int* __restrict__ pad_out,
                               float* __restrict__ ze_out) {
    int r = blockIdx.x * blockDim.y + threadIdx.y;
    int lane = threadIdx.x;
    const float* row = src + (size_t)r * ncols;
    float s = 0.f;
    for (int j = lane; j < ncols; j += 32) { float v = row[j]; s = fmaf(v, v, s); }
    #pragma unroll
    for (int o = 16; o; o >>= 1) s += __shfl_down_sync(0xffffffffu, s, o);
    s = __shfl_sync(0xffffffffu, s, 0);
    int pd = 0;
    if (pad_out) {
        pd = (sqrtf(s) <= 1e-6f) ? 1 : 0;
        if (lane == 0) pad_out[r] = pd;
    }
    if (ze_out) {
        for (int j = lane; j < ncols; j += 32)
            ze_out[(size_t)r * ncols + j] = pd ? 0.f : row[j];
    }
    if (lane == 0) norm_out[r] = pd ? 0.f : s;
}

// ---------------- generic NT GEMM: C = A[M,K] @ B[N,K]^T (+epilogue) -------
// EPI: 0 = +bias, 1 = +bias,relu, 2 = VQ distance (xn[m]+cn[n]-2*acc)
template <int EPI>
__global__ __launch_bounds__(256, 2) void gemm_nt(
        const float* __restrict__ A, const float* __restrict__ B,
        const float* __restrict__ bias, float* __restrict__ C,
        int K, int ldc,
        const float* __restrict__ xn, const float* __restrict__ cn) {
    __shared__ float As[32][132];
    __shared__ float Bs[32][132];
    int m0 = blockIdx.y * 128, n0 = blockIdx.x * 128;
    int tid = threadIdx.x;
    int tm = tid >> 4, tn = tid & 15;
    float acc[8][8];
    #pragma unroll
    for (int i = 0; i < 8; i++)
        #pragma unroll
        for (int j = 0; j < 8; j++) acc[i][j] = 0.f;

    const float* Ag = A + (size_t)m0 * K;
    const float* Bg = B + (size_t)n0 * K;

    for (int kt = 0; kt < K; kt += 32) {
        #pragma unroll
        for (int i = 0; i < 4; i++) {
            int idx = tid + i * 256;
            int row = idx >> 3, c4 = (idx & 7) * 4;
            float4 va = *(const float4*)(Ag + (size_t)row * K + kt + c4);
            As[c4 + 0][row] = cvt_in(va.x); As[c4 + 1][row] = cvt_in(va.y);
            As[c4 + 2][row] = cvt_in(va.z); As[c4 + 3][row] = cvt_in(va.w);
            float4 vb = *(const float4*)(Bg + (size_t)row * K + kt + c4);
            Bs[c4 + 0][row] = cvt_in(vb.x); Bs[c4 + 1][row] = cvt_in(vb.y);
            Bs[c4 + 2][row] = cvt_in(vb.z); Bs[c4 + 3][row] = cvt_in(vb.w);
        }
        __syncthreads();
        #pragma unroll
        for (int k = 0; k < 32; k++) {
            float4 a0 = *(const float4*)&As[k][tm * 8];
            float4 a1 = *(const float4*)&As[k][tm * 8 + 4];
            float4 b0 = *(const float4*)&Bs[k][tn * 8];
            float4 b1 = *(const float4*)&Bs[k][tn * 8 + 4];
            float av[8] = {a0.x, a0.y, a0.z, a0.w, a1.x, a1.y, a1.z, a1.w};
            float bv[8] = {b0.x, b0.y, b0.z, b0.w, b1.x, b1.y, b1.z, b1.w};
            #pragma unroll
            for (int i = 0; i < 8; i++)
                #pragma unroll
                for (int j = 0; j < 8; j++)
                    acc[i][j] = fmaf(av[i], bv[j], acc[i][j]);
        }
        __syncthreads();
    }

    #pragma unroll
    for (int i = 0; i < 8; i++) {
        int m = m0 + tm * 8 + i;
        #pragma unroll
        for (int j = 0; j < 8; j++) {
            int n = n0 + tn * 8 + j;
            float v = acc[i][j];
            if (EPI == 2) {
                C[(size_t)m * ldc + n] = (xn[m] + cn[n]) - 2.0f * v;
            } else {
                v += bias[n];
                if (EPI == 1) v = fmaxf(v, 0.f);
                C[(size_t)m * ldc + n] = v;
            }
        }
    }
}

// ---------------- top-10 smallest per row (stable on (d, idx)) -------------
__global__ void topk_kernel(const float* __restrict__ dmat,
                            float* __restrict__ topd, int* __restrict__ topi) {
    int r = blockIdx.x, t = threadIdx.x;
    const float* row = dmat + (size_t)r * KCB;
    float vd[10]; int vi[10];
    #pragma unroll
    for (int c = 0; c < 10; c++) { vd[c] = __int_as_float(0x7f800000); vi[c] = 0x7fffffff; }
    for (int j = t; j < KCB; j += 256) {
        float d = row[j];
        if (d < vd[9]) {
            int p = 9;
            while (p > 0 && d < vd[p - 1]) { vd[p] = vd[p - 1]; vi[p] = vi[p - 1]; p--; }
            vd[p] = d; vi[p] = j;
        }
    }
    __shared__ float sd[2560];
    __shared__ int   si[2560];
    #pragma unroll
    for (int c = 0; c < 10; c++) { sd[t * 10 + c] = vd[c]; si[t * 10 + c] = vi[c]; }
    __syncthreads();
    if (t == 0) {
        float fd[10]; int fi[10];
        #pragma unroll
        for (int c = 0; c < 10; c++) { fd[c] = __int_as_float(0x7f800000); fi[c] = 0x7fffffff; }
        for (int q = 0; q < 2560; q++) {
            float d = sd[q]; int ix = si[q];
            if (d < fd[9] || (d == fd[9] && ix < fi[9])) {
                int p = 9;
                while (p > 0 && (d < fd[p - 1] || (d == fd[p - 1] && ix < fi[p - 1]))) {
                    fd[p] = fd[p - 1]; fi[p] = fi[p - 1]; p--;
                }
                fd[p] = d; fi[p] = ix;
            }
        }
        #pragma unroll
        for (int c = 0; c < 10; c++) { topd[r * 10 + c] = fd[c]; topi[r * 10 + c] = fi[c]; }
    }
}

// ---------------- threefry2x32, PARTITIONABLE path (JAX >= 0.4.36 default) -
// per element i: counter pair = (uint32(i >> 32), uint32(i)) = (0, i)
// 32-bit draw  = out0 ^ out1
__device__ __forceinline__ uint32_t rotl32(uint32_t v, int d) {
    return (v << d) | (v >> (32 - d));
}
__device__ __forceinline__ float bits_to_gumbel(uint32_t bits) {
    float u = __uint_as_float((bits >> 9) | 0x3f800000u) - 1.0f;
    u = fmaxf(1e-10f, u + 1e-10f);   // floats*(maxval-minval)+minval, then lax.max
    return -logf(-logf(u));
}
__global__ void gumbel_kernel(float* __restrict__ gum) {
    int i = blockIdx.x * 256 + threadIdx.x;
    if (i >= NTOK * 10) return;
    const uint32_t ks0 = 0u, ks1 = 42u, ks2 = 0u ^ 42u ^ 0x1BD11BDAu;
    uint32_t ks[3] = {ks0, ks1, ks2};
    uint32_t x0 = 0u + ks0;              // hi word of 64-bit counter = 0
    uint32_t x1 = (uint32_t)i + ks1;     // lo word = i
    const int r0[4] = {13, 15, 26, 6}, r1[4] = {17, 29, 16, 24};
    #pragma unroll
    for (int r = 0; r < 5; r++) {
        const int* rr = (r & 1) ? r1 : r0;
        #pragma unroll
        for (int q = 0; q < 4; q++) { x0 += x1; x1 = rotl32(x1, rr[q]); x1 ^= x0; }
        x0 += ks[(r + 1) % 3];
        x1 += ks[(r + 2) % 3] + (uint32_t)(r + 1);
    }
    gum[i] = bits_to_gumbel(x0 ^ x1);
}

// ---------------- gumbel-argmax over top-10, then straight-through ---------
__global__ void choose_quant(const float* __restrict__ topd, const int* __restrict__ topi,
                             const float* __restrict__ gum, const float* __restrict__ cb,
                             const float* __restrict__ ze, float* __restrict__ h) {
    int r = blockIdx.x;
    __shared__ int es;
    if (threadIdx.x == 0) {
        float best = -__int_as_float(0x7f800000); int bc = 0;
        for (int c = 0; c < 10; c++) {
            float v = (-topd[r * 10 + c]) / 1.0f + gum[r * 10 + c];
            if (v > best) { best = v; bc = c; }
        }
        es = topi[r * 10 + bc];
    }
    __syncthreads();
    int e = es;
    for (int j = threadIdx.x; j < DIM; j += blockDim.x) {
        float z = ze[(size_t)r * DIM + j];
        h[(size_t)r * DIM + j] = z + (cb[(size_t)e * DIM + j] - z);
    }
}

// ---------------- attention: scores = QK^T / sqrt(96) + bias ---------------
__global__ __launch_bounds__(256, 2) void attn_scores(
        const float* __restrict__ qb, const float* __restrict__ kb,
        float* __restrict__ sc, const int* __restrict__ pad, int self_mask) {
    __shared__ float Qs[32][68];
    __shared__ float Ks[32][132];
    int bh = blockIdx.z, b = bh >> 3, h = bh & 7;
    const float* Q  = qb + (size_t)b * SEQ * (3 * DIM) + h * DH;
    const float* Kp = kb + (size_t)b * SEQ * (3 * DIM) + h * DH;
    int q0 = blockIdx.y * 64, k0 = blockIdx.x * 128;
    int tid = threadIdx.x;
    int tq = tid >> 5, tk = tid & 31;
    float acc[8][4];
    #pragma unroll
    for (int i = 0; i < 8; i++)
        #pragma unroll
        for (int j = 0; j < 4; j++) acc[i][j] = 0.f;

    for (int c = 0; c < DH; c += 32) {
        #pragma unroll
        for (int i = 0; i < 2; i++) {
            int idx = tid + i * 256;
            int row = idx >> 3, c4 = (idx & 7) * 4;
            float4 v = *(const float4*)(Q + (size_t)(q0 + row) * (3 * DIM) + c + c4);
            Qs[c4 + 0][row] = cvt_in(v.x); Qs[c4 + 1][row] = cvt_in(v.y);
            Qs[c4 + 2][row] = cvt_in(v.z); Qs[c4 + 3][row] = cvt_in(v.w);
        }
        #pragma unroll
        for (int i = 0; i < 4; i++) {
            int idx = tid + i * 256;
            int row = idx >> 3, c4 = (idx & 7) * 4;
            float4 v = *(const float4*)(Kp + (size_t)(k0 + row) * (3 * DIM) + c + c4);
            Ks[c4 + 0][row] = cvt_in(v.x); Ks[c4 + 1][row] = cvt_in(v.y);
            Ks[c4 + 2][row] = cvt_in(v.z); Ks[c4 + 3][row] = cvt_in(v.w);
        }
        __syncthreads();
        #pragma unroll
        for (int k = 0; k < 32; k++) {
            float4 a0 = *(const float4*)&Qs[k][tq * 8];
            float4 a1 = *(const float4*)&Qs[k][tq * 8 + 4];
            float4 bb = *(const float4*)&Ks[k][tk * 4];
            float av[8] = {a0.x, a0.y, a0.z, a0.w, a1.x, a1.y, a1.z, a1.w};
            float bv[4] = {bb.x, bb.y, bb.z, bb.w};
            #pragma unroll
            for (int i = 0; i < 8; i++)
                #pragma unroll
                for (int j = 0; j < 4; j++)
                    acc[i][j] = fmaf(av[i], bv[j], acc[i][j]);
        }
        __syncthreads();
    }
    #pragma unroll
    for (int i = 0; i < 8; i++) {
        int q = q0 + tq * 8 + i;
        #pragma unroll
        for (int j = 0; j < 4; j++) {
            int kk = k0 + tk * 4 + j;
            float s = acc[i][j] / 9.797958971132712f;  // sqrt(96)
            if (self_mask && kk < q) s += NEGF;        // anti-causal mask (triu-transpose)
            if (pad[b * SEQ + kk]) s += NEGF;
            sc[((size_t)bh * SEQ + q) * SEQ + kk] = s;
        }
    }
}

// ---------------- softmax over rows of 512 (warp per row) ------------------
__global__ void softmax_rows(float* __restrict__ sc) {
    int row = blockIdx.x * 8 + threadIdx.y;
    int lane = threadIdx.x;
    float* p = sc + (size_t)row * SEQ;
    float v[16];
    float m = -__int_as_float(0x7f800000);
    #pragma unroll
    for (int t = 0; t < 16; t++) { v[t] = p[lane + t * 32]; m = fmaxf(m, v[t]); }
    #pragma unroll
    for (int o = 16; o; o >>= 1) m = fmaxf(m, __shfl_xor_sync(0xffffffffu, m, o));
    float s = 0.f;
    #pragma unroll
    for (int t = 0; t < 16; t++) { v[t] = expf(v[t] - m); s += v[t]; }
    #pragma unroll
    for (int o = 16; o; o >>= 1) s += __shfl_xor_sync(0xffffffffu, s, o);
    #pragma unroll
    for (int t = 0; t < 16; t++) p[lane + t * 32] = v[t] / s;
}

// ---------------- attention: O = P @ V  (per b,h: 512x96x512) --------------
__global__ __launch_bounds__(256, 2) void attn_pv(
        const float* __restrict__ sc, const float* __restrict__ vb,
        float* __restrict__ out) {
    __shared__ float Ps[32][68];
    __shared__ float Vs[32][100];
    int bh = blockIdx.z, b = bh >> 3, h = bh & 7;
    const float* P = sc + (size_t)bh * SEQ * SEQ;
    const float* V = vb + (size_t)b * SEQ * (3 * DIM) + h * DH;
    int q0 = blockIdx.y * 64;
    int tid = threadIdx.x, tq = tid >> 4, tn = tid & 15;
    float acc[4][6];
    #pragma unroll
    for (int i = 0; i < 4; i++)
        #pragma unroll
        for (int j = 0; j < 6; j++) acc[i][j] = 0.f;

    for (int c = 0; c < SEQ; c += 32) {
        #pragma unroll
        for (int i = 0; i < 2; i++) {
            int idx = tid + i * 256;
            int row = idx >> 3, c4 = (idx & 7) * 4;
            float4 v = *(const float4*)(P + (size_t)(q0 + row) * SEQ + c + c4);
            Ps[c4 + 0][row] = cvt_in(v.x); Ps[c4 + 1][row] = cvt_in(v.y);
            Ps[c4 + 2][row] = cvt_in(v.z); Ps[c4 + 3][row] = cvt_in(v.w);
        }
        #pragma unroll
        for (int i = 0; i < 3; i++) {
            int idx = tid + i * 256;          // 0..767
            int row = idx / 24, cc = (idx % 24) * 4;
            float4 v = *(const float4*)(V + (size_t)(c + row) * (3 * DIM) + cc);
            Vs[row][cc + 0] = cvt_in(v.x); Vs[row][cc + 1] = cvt_in(v.y);
            Vs[row][cc + 2] = cvt_in(v.z); Vs[row][cc + 3] = cvt_in(v.w);
        }
        __syncthreads();
        #pragma unroll
        for (int k = 0; k < 32; k++) {
            float4 a0 = *(const float4*)&Ps[k][tq * 4];
            float av[4] = {a0.x, a0.y, a0.z, a0.w};
            float bv[6];
            #pragma unroll
            for (int j = 0; j < 6; j++) bv[j] = Vs[k][tn * 6 + j];
            #pragma unroll
            for (int i = 0; i < 4; i++)
                #pragma unroll
                for (int j = 0; j < 6; j++)
                    acc[i][j] = fmaf(av[i], bv[j], acc[i][j]);
        }
        __syncthreads();
    }
    #pragma unroll
    for (int i = 0; i < 4; i++) {
        int q = q0 + tq * 4 + i;
        #pragma unroll
        for (int j = 0; j < 6; j++) {
            int d = tn * 6 + j;
            out[(size_t)(b * SEQ + q) * DIM + h * DH + d] = acc[i][j];
        }
    }
}

// ---------------- residual add + LayerNorm (in-place on h) ----------------
__device__ __forceinline__ float blksum(float v, float* red) {
    #pragma unroll
    for (int o = 16; o; o >>= 1) v += __shfl_down_sync(0xffffffffu, v, o);
    if ((threadIdx.x & 31) == 0) red[threadIdx.x >> 5] = v;
    __syncthreads();
    if (threadIdx.x == 0) {
        float s = red[0];
        #pragma unroll
        for (int w = 1; w < 8; w++) s += red[w];
        red[0] = s;
    }
    __syncthreads();
    float s = red[0];
    __syncthreads();
    return s;
}

__global__ void ln_kernel(float* __restrict__ h, const float* __restrict__ delta,
                          const float* __restrict__ g, const float* __restrict__ b) {
    __shared__ float xs[DIM];
    __shared__ float red[8];
    int r = blockIdx.x, tid = threadIdx.x;
    float part = 0.f;
    #pragma unroll
    for (int t = 0; t < 3; t++) {
        int j = tid + t * 256;
        float x = h[(size_t)r * DIM + j] + delta[(size_t)r * DIM + j];
        xs[j] = x; part += x;
    }
    float mean = blksum(part, red) / 768.0f;
    part = 0.f;
    #pragma unroll
    for (int t = 0; t < 3; t++) {
        int j = tid + t * 256;
        float d = xs[j] - mean; part += d * d;
    }
    float var = blksum(part, red) / 768.0f;
    float s = sqrtf(var + 1e-5f);
    #pragma unroll
    for (int t = 0; t < 3; t++) {
        int j = tid + t * 256;
        h[(size_t)r * DIM + j] = (xs[j] - mean) / s * g[j] + b[j];
    }
}

// ===========================================================================
extern "C" void kernel_launch(void* const* d_in, const int* in_sizes, int n_in,
                              void* d_out, int out_size) {
    const float* x       = (const float*)d_in[0];
    const float* cb      = (const float*)d_in[1];
    const float* sa_in_w = (const float*)d_in[2];
    const float* sa_in_b = (const float*)d_in[3];
    const float* sa_ow   = (const float*)d_in[4];
    const float* sa_ob   = (const float*)d_in[5];
    const float* ca_in_w = (const float*)d_in[6];
    const float* ca_in_b = (const float*)d_in[7];
    const float* ca_ow   = (const float*)d_in[8];
    const float* ca_ob   = (const float*)d_in[9];
    const float* ln1g    = (const float*)d_in[10];
    const float* ln1b    = (const float*)d_in[11];
    const float* ln2g    = (const float*)d_in[12];
    const float* ln2b    = (const float*)d_in[13];
    const float* ln3g    = (const float*)d_in[14];
    const float* ln3b    = (const float*)d_in[15];
    const float* ffw1    = (const float*)d_in[16];
    const float* ffb1    = (const float*)d_in[17];
    const float* ffw2    = (const float*)d_in[18];
    const float* ffb2    = (const float*)d_in[19];
    const float* outw    = (const float*)d_in[20];
    const float* outb    = (const float*)d_in[21];
    float* out = (float*)d_out;

    float *ze, *xn, *cn, *big, *topd, *gum, *h, *qkv, *attn, *tmp, *ffb;
    int *pad, *topi;
    cudaGetSymbolAddress((void**)&ze,   g_ze);
    cudaGetSymbolAddress((void**)&xn,   g_xnorm);
    cudaGetSymbolAddress((void**)&pad,  g_pad);
    cudaGetSymbolAddress((void**)&cn,   g_cnorm);
    cudaGetSymbolAddress((void**)&big,  g_big);
    cudaGetSymbolAddress((void**)&topd, g_topd);
    cudaGetSymbolAddress((void**)&topi, g_topi);
    cudaGetSymbolAddress((void**)&gum,  g_gum);
    cudaGetSymbolAddress((void**)&h,    g_h);
    cudaGetSymbolAddress((void**)&qkv,  g_qkv);
    cudaGetSymbolAddress((void**)&attn, g_attn);
    cudaGetSymbolAddress((void**)&tmp,  g_tmp);
    cudaGetSymbolAddress((void**)&ffb,  g_ffb);

    dim3 w32x8(32, 8);

    // --- VQ ---
    rownorm_kernel<<<NTOK / 8, w32x8>>>(x, DIM, xn, pad, ze);
    rownorm_kernel<<<KCB / 8, w32x8>>>(cb, DIM, cn, nullptr, nullptr);
    gemm_nt<2><<<dim3(64, 64), 256>>>(ze, cb, nullptr, big, DIM, KCB, xn, cn);
    topk_kernel<<<NTOK, 256>>>(big, topd, topi);
    gumbel_kernel<<<(NTOK * 10 + 255) / 256, 256>>>(gum);
    choose_quant<<<NTOK, 128>>>(topd, topi, gum, cb, ze, h);

    // --- decoder layers ---
    for (int l = 0; l < NLAYER; l++) {
        const float* saw = sa_in_w + (size_t)l * 3 * DIM * DIM;
        const float* sab = sa_in_b + (size_t)l * 3 * DIM;
        const float* sow = sa_ow + (size_t)l * DIM * DIM;
        const float* sob = sa_ob + (size_t)l * DIM;
        const float* caw = ca_in_w + (size_t)l * 3 * DIM * DIM;
        const float* cab = ca_in_b + (size_t)l * 3 * DIM;
        const float* cow = ca_ow + (size_t)l * DIM * DIM;
        const float* cob = ca_ob + (size_t)l * DIM;

        // self-attention
        gemm_nt<0><<<dim3(18, 64), 256>>>(h, saw, sab, qkv, DIM, 3 * DIM, nullptr, nullptr);
        attn_scores<<<dim3(4, 8, 128), 256>>>(qkv, qkv + DIM, big, pad, 1);
        softmax_rows<<<BATCH * NHEAD * SEQ / 8, w32x8>>>(big);
        attn_pv<<<dim3(1, 8, 128), 256>>>(big, qkv + 2 * DIM, attn);
        gemm_nt<0><<<dim3(6, 64), 256>>>(attn, sow, sob, tmp, DIM, DIM, nullptr, nullptr);
        ln_kernel<<<NTOK, 256>>>(h, tmp, ln1g + l * DIM, ln1b + l * DIM);

        // cross-attention (memory = z_e)
        gemm_nt<0><<<dim3(6, 64), 256>>>(h, caw, cab, qkv, DIM, 3 * DIM, nullptr, nullptr);
        gemm_nt<0><<<dim3(12, 64), 256>>>(ze, caw + (size_t)DIM * DIM, cab + DIM,
                                          qkv + DIM, DIM, 3 * DIM, nullptr, nullptr);
        attn_scores<<<dim3(4, 8, 128), 256>>>(qkv, qkv + DIM, big, pad, 0);
        softmax_rows<<<BATCH * NHEAD * SEQ / 8, w32x8>>>(big);
        attn_pv<<<dim3(1, 8, 128), 256>>>(big, qkv + 2 * DIM, attn);
        gemm_nt<0><<<dim3(6, 64), 256>>>(attn, cow, cob, tmp, DIM, DIM, nullptr, nullptr);
        ln_kernel<<<NTOK, 256>>>(h, tmp, ln2g + l * DIM, ln2b + l * DIM);

        // feed-forward
        gemm_nt<1><<<dim3(16, 64), 256>>>(h, ffw1 + (size_t)l * FFD * DIM,
                                          ffb1 + (size_t)l * FFD, ffb, DIM, FFD, nullptr, nullptr);
        gemm_nt<0><<<dim3(6, 64), 256>>>(ffb, ffw2 + (size_t)l * DIM * FFD,
                                         ffb2 + (size_t)l * DIM, tmp, FFD, DIM, nullptr, nullptr);
        ln_kernel<<<NTOK, 256>>>(h, tmp, ln3g + l * DIM, ln3b + l * DIM);
    }

    // --- output projection ---
    gemm_nt<0><<<dim3(6, 64), 256>>>(h, outw, outb, out, DIM, DIM, nullptr, nullptr);
}

// round 12
// speedup vs baseline: 1.1262x; 1.1262x over previous
#include <cuda_runtime.h>
#include <math.h>
#include <stdint.h>

#define NTOK 8192
#define DIM  768
#define KCB  8192
#define NHEAD 8
#define DH   96
#define SEQ  512
#define BATCH 16
#define NLAYER 6
#define FFD  2048
#define NEGF (-1e9f)

// ---------------- scratch (device globals: allocation-free contract) -------
__device__ float g_ze[(size_t)NTOK * DIM];
__device__ float g_xnorm[NTOK];
__device__ int   g_pad[NTOK];
__device__ float g_cnorm[KCB];
__device__ float g_big[(size_t)NTOK * KCB];     // VQ distances, then attn scores
__device__ float g_topd[NTOK * 10];
__device__ int   g_topi[NTOK * 10];
__device__ float g_gum[NTOK * 10];
__device__ float g_h[(size_t)NTOK * DIM];
__device__ float g_qkv[(size_t)NTOK * 3 * DIM];
__device__ float g_attn[(size_t)NTOK * DIM];
__device__ float g_tmp[(size_t)NTOK * DIM];
__device__ float g_ffb[(size_t)NTOK * FFD];

__device__ __forceinline__ float tf32r(float x) {
    uint32_t u = __float_as_uint(x), y;
    asm("cvt.rna.tf32.f32 %0, %1;" : "=r"(y) : "r"(u));
    return __uint_as_float(y);
}

// ---------------- row sumsq (+ optional pad mask and masked copy) ----------
__global__ void rownorm_kernel(const float* __restrict__ src, int ncols,
                               float* __restrict__ norm_out,
                               int* __restrict__ pad_out,
                               float* __restrict__ ze_out) {
    int r = blockIdx.x * blockDim.y + threadIdx.y;
    int lane = threadIdx.x;
    const float* row = src + (size_t)r * ncols;
    float s = 0.f;
    for (int j = lane; j < ncols; j += 32) { float v = row[j]; s = fmaf(v, v, s); }
    #pragma unroll
    for (int o = 16; o; o >>= 1) s += __shfl_down_sync(0xffffffffu, s, o);
    s = __shfl_sync(0xffffffffu, s, 0);
    int pd = 0;
    if (pad_out) {
        pd = (sqrtf(s) <= 1e-6f) ? 1 : 0;
        if (lane == 0) pad_out[r] = pd;
    }
    if (ze_out) {
        for (int j = lane; j < ncols; j += 32)
            ze_out[(size_t)r * ncols + j] = pd ? 0.f : row[j];
    }
    if (lane == 0) norm_out[r] = pd ? 0.f : s;
}

// ================= FFMA NT GEMM (VQ distance path — proven zero-flip) ======
// EPI: 2 = VQ distance (xn[m]+cn[n]-2*acc)
__global__ __launch_bounds__(256, 2) void gemm_nt_vq(
        const float* __restrict__ A, const float* __restrict__ B,
        float* __restrict__ C, int K, int ldc,
        const float* __restrict__ xn, const float* __restrict__ cn) {
    __shared__ float As[32][132];
    __shared__ float Bs[32][132];
    int m0 = blockIdx.y * 128, n0 = blockIdx.x * 128;
    int tid = threadIdx.x;
    int tm = tid >> 4, tn = tid & 15;
    float acc[8][8];
    #pragma unroll
    for (int i = 0; i < 8; i++)
        #pragma unroll
        for (int j = 0; j < 8; j++) acc[i][j] = 0.f;

    const float* Ag = A + (size_t)m0 * K;
    const float* Bg = B + (size_t)n0 * K;

    for (int kt = 0; kt < K; kt += 32) {
        #pragma unroll
        for (int i = 0; i < 4; i++) {
            int idx = tid + i * 256;
            int row = idx >> 3, c4 = (idx & 7) * 4;
            float4 va = *(const float4*)(Ag + (size_t)row * K + kt + c4);
            As[c4 + 0][row] = va.x; As[c4 + 1][row] = va.y;
            As[c4 + 2][row] = va.z; As[c4 + 3][row] = va.w;
            float4 vb = *(const float4*)(Bg + (size_t)row * K + kt + c4);
            Bs[c4 + 0][row] = vb.x; Bs[c4 + 1][row] = vb.y;
            Bs[c4 + 2][row] = vb.z; Bs[c4 + 3][row] = vb.w;
        }
        __syncthreads();
        #pragma unroll
        for (int k = 0; k < 32; k++) {
            float4 a0 = *(const float4*)&As[k][tm * 8];
            float4 a1 = *(const float4*)&As[k][tm * 8 + 4];
            float4 b0 = *(const float4*)&Bs[k][tn * 8];
            float4 b1 = *(const float4*)&Bs[k][tn * 8 + 4];
            float av[8] = {a0.x, a0.y, a0.z, a0.w, a1.x, a1.y, a1.z, a1.w};
            float bv[8] = {b0.x, b0.y, b0.z, b0.w, b1.x, b1.y, b1.z, b1.w};
            #pragma unroll
            for (int i = 0; i < 8; i++)
                #pragma unroll
                for (int j = 0; j < 8; j++)
                    acc[i][j] = fmaf(av[i], bv[j], acc[i][j]);
        }
        __syncthreads();
    }

    #pragma unroll
    for (int i = 0; i < 8; i++) {
        int m = m0 + tm * 8 + i;
        #pragma unroll
        for (int j = 0; j < 8; j++) {
            int n = n0 + tn * 8 + j;
            C[(size_t)m * ldc + n] = (xn[m] + cn[n]) - 2.0f * acc[i][j];
        }
    }
}

// ================= 3xTF32 tensor-core NT GEMM (decoder path) ===============
// C = A[M,K] @ B[N,K]^T, fp32-accurate via hi/lo TF32 split (3 mma passes).
// Block 128x128, k-step 32. 8 warps: warp (wm 0..1)x(wn 0..3) -> 64x32 tile.
// EPI: 0 = +bias, 1 = +bias,relu
#define SMEM_MMA (4 * 128 * 44 * 4)

#define MMA_TF32(cc, aa, bb) \
    asm volatile("mma.sync.aligned.m16n8k8.row.col.f32.tf32.tf32.f32 " \
        "{%0,%1,%2,%3}, {%4,%5,%6,%7}, {%8,%9}, {%0,%1,%2,%3};" \
        : "+f"(cc[0]), "+f"(cc[1]), "+f"(cc[2]), "+f"(cc[3]) \
        : "r"(aa[0]), "r"(aa[1]), "r"(aa[2]), "r"(aa[3]), \
          "r"(bb[0]), "r"(bb[1]))

template <int EPI>
__global__ __launch_bounds__(256) void gemm_nt_mma(
        const float* __restrict__ A, const float* __restrict__ B,
        const float* __restrict__ bias, float* __restrict__ C,
        int K, int ldc) {
    extern __shared__ float sm[];
    float* sAhi = sm;
    float* sAlo = sm + 128 * 44;
    float* sBhi = sm + 2 * 128 * 44;
    float* sBlo = sm + 3 * 128 * 44;

    const int tid  = threadIdx.x;
    const int wid  = tid >> 5, lane = tid & 31;
    const int grp  = lane >> 2, qr = lane & 3;
    const int wm   = wid >> 2, wn = wid & 3;
    const int m0   = blockIdx.y * 128, n0 = blockIdx.x * 128;

    float c[4][4][4];
    #pragma unroll
    for (int a = 0; a < 4; a++)
        #pragma unroll
        for (int b = 0; b < 4; b++)
            #pragma unroll
            for (int d = 0; d < 4; d++) c[a][b][d] = 0.f;

    const float* Ag = A + (size_t)m0 * K;
    const float* Bg = B + (size_t)n0 * K;

    for (int kt = 0; kt < K; kt += 32) {
        // ---- stage hi/lo tiles ----
        #pragma unroll
        for (int i = 0; i < 4; i++) {
            int idx = tid + i * 256;            // 0..1023
            int row = idx >> 3, c4 = (idx & 7) * 4;
            float4 va = *(const float4*)(Ag + (size_t)row * K + kt + c4);
            float4 hi, lo;
            hi.x = tf32r(va.x); lo.x = tf32r(va.x - hi.x);
            hi.y = tf32r(va.y); lo.y = tf32r(va.y - hi.y);
            hi.z = tf32r(va.z); lo.z = tf32r(va.z - hi.z);
            hi.w = tf32r(va.w); lo.w = tf32r(va.w - hi.w);
            *(float4*)(sAhi + row * 44 + c4) = hi;
            *(float4*)(sAlo + row * 44 + c4) = lo;
            float4 vb = *(const float4*)(Bg + (size_t)row * K + kt + c4);
            hi.x = tf32r(vb.x); lo.x = tf32r(vb.x - hi.x);
            hi.y = tf32r(vb.y); lo.y = tf32r(vb.y - hi.y);
            hi.z = tf32r(vb.z); lo.z = tf32r(vb.z - hi.z);
            hi.w = tf32r(vb.w); lo.w = tf32r(vb.w - hi.w);
            *(float4*)(sBhi + row * 44 + c4) = hi;
            *(float4*)(sBlo + row * 44 + c4) = lo;
        }
        __syncthreads();

        // ---- compute ----
        #pragma unroll
        for (int k8 = 0; k8 < 4; k8++) {
            const int kb = k8 * 8 + qr;
            uint32_t ahi[4][4], alo[4][4], bhi[4][2], blo[4][2];
            #pragma unroll
            for (int mt = 0; mt < 4; mt++) {
                int r0 = (wm * 64 + mt * 16 + grp) * 44 + kb;
                ahi[mt][0] = __float_as_uint(sAhi[r0]);
                ahi[mt][1] = __float_as_uint(sAhi[r0 + 8 * 44]);
                ahi[mt][2] = __float_as_uint(sAhi[r0 + 4]);
                ahi[mt][3] = __float_as_uint(sAhi[r0 + 8 * 44 + 4]);
                alo[mt][0] = __float_as_uint(sAlo[r0]);
                alo[mt][1] = __float_as_uint(sAlo[r0 + 8 * 44]);
                alo[mt][2] = __float_as_uint(sAlo[r0 + 4]);
                alo[mt][3] = __float_as_uint(sAlo[r0 + 8 * 44 + 4]);
            }
            #pragma unroll
            for (int nt = 0; nt < 4; nt++) {
                int r0 = (wn * 32 + nt * 8 + grp) * 44 + kb;
                bhi[nt][0] = __float_as_uint(sBhi[r0]);
                bhi[nt][1] = __float_as_uint(sBhi[r0 + 4]);
                blo[nt][0] = __float_as_uint(sBlo[r0]);
                blo[nt][1] = __float_as_uint(sBlo[r0 + 4]);
            }
            #pragma unroll
            for (int mt = 0; mt < 4; mt++)
                #pragma unroll
                for (int nt = 0; nt < 4; nt++) {
                    MMA_TF32(c[mt][nt], ahi[mt], blo[nt]);
                    MMA_TF32(c[mt][nt], alo[mt], bhi[nt]);
                    MMA_TF32(c[mt][nt], ahi[mt], bhi[nt]);
                }
        }
        __syncthreads();
    }

    // ---- epilogue ----
    #pragma unroll
    for (int mt = 0; mt < 4; mt++) {
        int mrow = m0 + wm * 64 + mt * 16 + grp;
        #pragma unroll
        for (int nt = 0; nt < 4; nt++) {
            int ncol = n0 + wn * 32 + nt * 8 + qr * 2;
            float v0 = c[mt][nt][0], v1 = c[mt][nt][1];
            float v2 = c[mt][nt][2], v3 = c[mt][nt][3];
            float b0 = bias[ncol], b1 = bias[ncol + 1];
            v0 += b0; v1 += b1; v2 += b0; v3 += b1;
            if (EPI == 1) {
                v0 = fmaxf(v0, 0.f); v1 = fmaxf(v1, 0.f);
                v2 = fmaxf(v2, 0.f); v3 = fmaxf(v3, 0.f);
            }
            *(float2*)(C + (size_t)mrow * ldc + ncol)       = make_float2(v0, v1);
            *(float2*)(C + (size_t)(mrow + 8) * ldc + ncol) = make_float2(v2, v3);
        }
    }
}

// ---------------- top-10 smallest per row (stable on (d, idx)) -------------
__global__ void topk_kernel(const float* __restrict__ dmat,
                            float* __restrict__ topd, int* __restrict__ topi) {
    int r = blockIdx.x, t = threadIdx.x;
    const float* row = dmat + (size_t)r * KCB;
    float vd[10]; int vi[10];
    #pragma unroll
    for (int c = 0; c < 10; c++) { vd[c] = __int_as_float(0x7f800000); vi[c] = 0x7fffffff; }
    for (int j = t; j < KCB; j += 256) {
        float d = row[j];
        if (d < vd[9]) {
            int p = 9;
            while (p > 0 && d < vd[p - 1]) { vd[p] = vd[p - 1]; vi[p] = vi[p - 1]; p--; }
            vd[p] = d; vi[p] = j;
        }
    }
    __shared__ float sd[2560];
    __shared__ int   si[2560];
    #pragma unroll
    for (int c = 0; c < 10; c++) { sd[t * 10 + c] = vd[c]; si[t * 10 + c] = vi[c]; }
    __syncthreads();
    if (t == 0) {
        float fd[10]; int fi[10];
        #pragma unroll
        for (int c = 0; c < 10; c++) { fd[c] = __int_as_float(0x7f800000); fi[c] = 0x7fffffff; }
        for (int q = 0; q < 2560; q++) {
            float d = sd[q]; int ix = si[q];
            if (d < fd[9] || (d == fd[9] && ix < fi[9])) {
                int p = 9;
                while (p > 0 && (d < fd[p - 1] || (d == fd[p - 1] && ix < fi[p - 1]))) {
                    fd[p] = fd[p - 1]; fi[p] = fi[p - 1]; p--;
                }
                fd[p] = d; fi[p] = ix;
            }
        }
        #pragma unroll
        for (int c = 0; c < 10; c++) { topd[r * 10 + c] = fd[c]; topi[r * 10 + c] = fi[c]; }
    }
}

// ---------------- threefry2x32, PARTITIONABLE path (JAX >= 0.4.36 default) -
__device__ __forceinline__ uint32_t rotl32(uint32_t v, int d) {
    return (v << d) | (v >> (32 - d));
}
__device__ __forceinline__ float bits_to_gumbel(uint32_t bits) {
    float u = __uint_as_float((bits >> 9) | 0x3f800000u) - 1.0f;
    u = fmaxf(1e-10f, u + 1e-10f);
    return -logf(-logf(u));
}
__global__ void gumbel_kernel(float* __restrict__ gum) {
    int i = blockIdx.x * 256 + threadIdx.x;
    if (i >= NTOK * 10) return;
    const uint32_t ks0 = 0u, ks1 = 42u, ks2 = 0u ^ 42u ^ 0x1BD11BDAu;
    uint32_t ks[3] = {ks0, ks1, ks2};
    uint32_t x0 = 0u + ks0;
    uint32_t x1 = (uint32_t)i + ks1;
    const int r0[4] = {13, 15, 26, 6}, r1[4] = {17, 29, 16, 24};
    #pragma unroll
    for (int r = 0; r < 5; r++) {
        const int* rr = (r & 1) ? r1 : r0;
        #pragma unroll
        for (int q = 0; q < 4; q++) { x0 += x1; x1 = rotl32(x1, rr[q]); x1 ^= x0; }
        x0 += ks[(r + 1) % 3];
        x1 += ks[(r + 2) % 3] + (uint32_t)(r + 1);
    }
    gum[i] = bits_to_gumbel(x0 ^ x1);
}

// ---------------- gumbel-argmax over top-10, then straight-through ---------
__global__ void choose_quant(const float* __restrict__ topd, const int* __restrict__ topi,
                             const float* __restrict__ gum, const float* __restrict__ cb,
                             const float* __restrict__ ze, float* __restrict__ h) {
    int r = blockIdx.x;
    __shared__ int es;
    if (threadIdx.x == 0) {
        float best = -__int_as_float(0x7f800000); int bc = 0;
        for (int c = 0; c < 10; c++) {
            float v = (-topd[r * 10 + c]) / 1.0f + gum[r * 10 + c];
            if (v > best) { best = v; bc = c; }
        }
        es = topi[r * 10 + bc];
    }
    __syncthreads();
    int e = es;
    for (int j = threadIdx.x; j < DIM; j += blockDim.x) {
        float z = ze[(size_t)r * DIM + j];
        h[(size_t)r * DIM + j] = z + (cb[(size_t)e * DIM + j] - z);
    }
}

// ---------------- attention: scores = QK^T / sqrt(96) + bias ---------------
__global__ __launch_bounds__(256, 2) void attn_scores(
        const float* __restrict__ qb, const float* __restrict__ kb,
        float* __restrict__ sc, const int* __restrict__ pad, int self_mask) {
    __shared__ float Qs[32][68];
    __shared__ float Ks[32][132];
    int bh = blockIdx.z, b = bh >> 3, h = bh & 7;
    const float* Q  = qb + (size_t)b * SEQ * (3 * DIM) + h * DH;
    const float* Kp = kb + (size_t)b * SEQ * (3 * DIM) + h * DH;
    int q0 = blockIdx.y * 64, k0 = blockIdx.x * 128;
    int tid = threadIdx.x;
    int tq = tid >> 5, tk = tid & 31;
    float acc[8][4];
    #pragma unroll
    for (int i = 0; i < 8; i++)
        #pragma unroll
        for (int j = 0; j < 4; j++) acc[i][j] = 0.f;

    for (int c = 0; c < DH; c += 32) {
        #pragma unroll
        for (int i = 0; i < 2; i++) {
            int idx = tid + i * 256;
            int row = idx >> 3, c4 = (idx & 7) * 4;
            float4 v = *(const float4*)(Q + (size_t)(q0 + row) * (3 * DIM) + c + c4);
            Qs[c4 + 0][row] = v.x; Qs[c4 + 1][row] = v.y;
            Qs[c4 + 2][row] = v.z; Qs[c4 + 3][row] = v.w;
        }
        #pragma unroll
        for (int i = 0; i < 4; i++) {
            int idx = tid + i * 256;
            int row = idx >> 3, c4 = (idx & 7) * 4;
            float4 v = *(const float4*)(Kp + (size_t)(k0 + row) * (3 * DIM) + c + c4);
            Ks[c4 + 0][row] = v.x; Ks[c4 + 1][row] = v.y;
            Ks[c4 + 2][row] = v.z; Ks[c4 + 3][row] = v.w;
        }
        __syncthreads();
        #pragma unroll
        for (int k = 0; k < 32; k++) {
            float4 a0 = *(const float4*)&Qs[k][tq * 8];
            float4 a1 = *(const float4*)&Qs[k][tq * 8 + 4];
            float4 bb = *(const float4*)&Ks[k][tk * 4];
            float av[8] = {a0.x, a0.y, a0.z, a0.w, a1.x, a1.y, a1.z, a1.w};
            float bv[4] = {bb.x, bb.y, bb.z, bb.w};
            #pragma unroll
            for (int i = 0; i < 8; i++)
                #pragma unroll
                for (int j = 0; j < 4; j++)
                    acc[i][j] = fmaf(av[i], bv[j], acc[i][j]);
        }
        __syncthreads();
    }
    #pragma unroll
    for (int i = 0; i < 8; i++) {
        int q = q0 + tq * 8 + i;
        #pragma unroll
        for (int j = 0; j < 4; j++) {
            int kk = k0 + tk * 4 + j;
            float s = acc[i][j] / 9.797958971132712f;  // sqrt(96)
            if (self_mask && kk < q) s += NEGF;        // anti-causal mask (triu-transpose)
            if (pad[b * SEQ + kk]) s += NEGF;
            sc[((size_t)bh * SEQ + q) * SEQ + kk] = s;
        }
    }
}

// ---------------- softmax over rows of 512 (warp per row) ------------------
__global__ void softmax_rows(float* __restrict__ sc) {
    int row = blockIdx.x * 8 + threadIdx.y;
    int lane = threadIdx.x;
    float* p = sc + (size_t)row * SEQ;
    float v[16];
    float m = -__int_as_float(0x7f800000);
    #pragma unroll
    for (int t = 0; t < 16; t++) { v[t] = p[lane + t * 32]; m = fmaxf(m, v[t]); }
    #pragma unroll
    for (int o = 16; o; o >>= 1) m = fmaxf(m, __shfl_xor_sync(0xffffffffu, m, o));
    float s = 0.f;
    #pragma unroll
    for (int t = 0; t < 16; t++) { v[t] = expf(v[t] - m); s += v[t]; }
    #pragma unroll
    for (int o = 16; o; o >>= 1) s += __shfl_xor_sync(0xffffffffu, s, o);
    #pragma unroll
    for (int t = 0; t < 16; t++) p[lane + t * 32] = v[t] / s;
}

// ---------------- attention: O = P @ V  (per b,h: 512x96x512) --------------
__global__ __launch_bounds__(256, 2) void attn_pv(
        const float* __restrict__ sc, const float* __restrict__ vb,
        float* __restrict__ out) {
    __shared__ float Ps[32][68];
    __shared__ float Vs[32][100];
    int bh = blockIdx.z, b = bh >> 3, h = bh & 7;
    const float* P = sc + (size_t)bh * SEQ * SEQ;
    const float* V = vb + (size_t)b * SEQ * (3 * DIM) + h * DH;
    int q0 = blockIdx.y * 64;
    int tid = threadIdx.x, tq = tid >> 4, tn = tid & 15;
    float acc[4][6];
    #pragma unroll
    for (int i = 0; i < 4; i++)
        #pragma unroll
        for (int j = 0; j < 6; j++) acc[i][j] = 0.f;

    for (int c = 0; c < SEQ; c += 32) {
        #pragma unroll
        for (int i = 0; i < 2; i++) {
            int idx = tid + i * 256;
            int row = idx >> 3, c4 = (idx & 7) * 4;
            float4 v = *(const float4*)(P + (size_t)(q0 + row) * SEQ + c + c4);
            Ps[c4 + 0][row] = v.x; Ps[c4 + 1][row] = v.y;
            Ps[c4 + 2][row] = v.z; Ps[c4 + 3][row] = v.w;
        }
        #pragma unroll
        for (int i = 0; i < 3; i++) {
            int idx = tid + i * 256;          // 0..767
            int row = idx / 24, cc = (idx % 24) * 4;
            float4 v = *(const float4*)(V + (size_t)(c + row) * (3 * DIM) + cc);
            Vs[row][cc + 0] = v.x; Vs[row][cc + 1] = v.y;
            Vs[row][cc + 2] = v.z; Vs[row][cc + 3] = v.w;
        }
        __syncthreads();
        #pragma unroll
        for (int k = 0; k < 32; k++) {
            float4 a0 = *(const float4*)&Ps[k][tq * 4];
            float av[4] = {a0.x, a0.y, a0.z, a0.w};
            float bv[6];
            #pragma unroll
            for (int j = 0; j < 6; j++) bv[j] = Vs[k][tn * 6 + j];
            #pragma unroll
            for (int i = 0; i < 4; i++)
                #pragma unroll
                for (int j = 0; j < 6; j++)
                    acc[i][j] = fmaf(av[i], bv[j], acc[i][j]);
        }
        __syncthreads();
    }
    #pragma unroll
    for (int i = 0; i < 4; i++) {
        int q = q0 + tq * 4 + i;
        #pragma unroll
        for (int j = 0; j < 6; j++) {
            int d = tn * 6 + j;
            out[(size_t)(b * SEQ + q) * DIM + h * DH + d] = acc[i][j];
        }
    }
}

// ---------------- residual add + LayerNorm (in-place on h) ----------------
__device__ __forceinline__ float blksum(float v, float* red) {
    #pragma unroll
    for (int o = 16; o; o >>= 1) v += __shfl_down_sync(0xffffffffu, v, o);
    if ((threadIdx.x & 31) == 0) red[threadIdx.x >> 5] = v;
    __syncthreads();
    if (threadIdx.x == 0) {
        float s = red[0];
        #pragma unroll
        for (int w = 1; w < 8; w++) s += red[w];
        red[0] = s;
    }
    __syncthreads();
    float s = red[0];
    __syncthreads();
    return s;
}

__global__ void ln_kernel(float* __restrict__ h, const float* __restrict__ delta,
                          const float* __restrict__ g, const float* __restrict__ b) {
    __shared__ float xs[DIM];
    __shared__ float red[8];
    int r = blockIdx.x, tid = threadIdx.x;
    float part = 0.f;
    #pragma unroll
    for (int t = 0; t < 3; t++) {
        int j = tid + t * 256;
        float x = h[(size_t)r * DIM + j] + delta[(size_t)r * DIM + j];
        xs[j] = x; part += x;
    }
    float mean = blksum(part, red) / 768.0f;
    part = 0.f;
    #pragma unroll
    for (int t = 0; t < 3; t++) {
        int j = tid + t * 256;
        float d = xs[j] - mean; part += d * d;
    }
    float var = blksum(part, red) / 768.0f;
    float s = sqrtf(var + 1e-5f);
    #pragma unroll
    for (int t = 0; t < 3; t++) {
        int j = tid + t * 256;
        h[(size_t)r * DIM + j] = (xs[j] - mean) / s * g[j] + b[j];
    }
}

// ===========================================================================
extern "C" void kernel_launch(void* const* d_in, const int* in_sizes, int n_in,
                              void* d_out, int out_size) {
    const float* x       = (const float*)d_in[0];
    const float* cb      = (const float*)d_in[1];
    const float* sa_in_w = (const float*)d_in[2];
    const float* sa_in_b = (const float*)d_in[3];
    const float* sa_ow   = (const float*)d_in[4];
    const float* sa_ob   = (const float*)d_in[5];
    const float* ca_in_w = (const float*)d_in[6];
    const float* ca_in_b = (const float*)d_in[7];
    const float* ca_ow   = (const float*)d_in[8];
    const float* ca_ob   = (const float*)d_in[9];
    const float* ln1g    = (const float*)d_in[10];
    const float* ln1b    = (const float*)d_in[11];
    const float* ln2g    = (const float*)d_in[12];
    const float* ln2b    = (const float*)d_in[13];
    const float* ln3g    = (const float*)d_in[14];
    const float* ln3b    = (const float*)d_in[15];
    const float* ffw1    = (const float*)d_in[16];
    const float* ffb1    = (const float*)d_in[17];
    const float* ffw2    = (const float*)d_in[18];
    const float* ffb2    = (const float*)d_in[19];
    const float* outw    = (const float*)d_in[20];
    const float* outb    = (const float*)d_in[21];
    float* out = (float*)d_out;

    float *ze, *xn, *cn, *big, *topd, *gum, *h, *qkv, *attn, *tmp, *ffb;
    int *pad, *topi;
    cudaGetSymbolAddress((void**)&ze,   g_ze);
    cudaGetSymbolAddress((void**)&xn,   g_xnorm);
    cudaGetSymbolAddress((void**)&pad,  g_pad);
    cudaGetSymbolAddress((void**)&cn,   g_cnorm);
    cudaGetSymbolAddress((void**)&big,  g_big);
    cudaGetSymbolAddress((void**)&topd, g_topd);
    cudaGetSymbolAddress((void**)&topi, g_topi);
    cudaGetSymbolAddress((void**)&gum,  g_gum);
    cudaGetSymbolAddress((void**)&h,    g_h);
    cudaGetSymbolAddress((void**)&qkv,  g_qkv);
    cudaGetSymbolAddress((void**)&attn, g_attn);
    cudaGetSymbolAddress((void**)&tmp,  g_tmp);
    cudaGetSymbolAddress((void**)&ffb,  g_ffb);

    // allow 90KB dynamic smem for the mma gemm (idempotent, capture-safe)
    cudaFuncSetAttribute(gemm_nt_mma<0>, cudaFuncAttributeMaxDynamicSharedMemorySize, SMEM_MMA);
    cudaFuncSetAttribute(gemm_nt_mma<1>, cudaFuncAttributeMaxDynamicSharedMemorySize, SMEM_MMA);

    dim3 w32x8(32, 8);

    // --- VQ (FFMA distances: proven zero-flip precision domain) ---
    rownorm_kernel<<<NTOK / 8, w32x8>>>(x, DIM, xn, pad, ze);
    rownorm_kernel<<<KCB / 8, w32x8>>>(cb, DIM, cn, nullptr, nullptr);
    gemm_nt_vq<<<dim3(64, 64), 256>>>(ze, cb, big, DIM, KCB, xn, cn);
    topk_kernel<<<NTOK, 256>>>(big, topd, topi);
    gumbel_kernel<<<(NTOK * 10 + 255) / 256, 256>>>(gum);
    choose_quant<<<NTOK, 128>>>(topd, topi, gum, cb, ze, h);

    // --- decoder layers (3xTF32 tensor-core gemms) ---
    for (int l = 0; l < NLAYER; l++) {
        const float* saw = sa_in_w + (size_t)l * 3 * DIM * DIM;
        const float* sab = sa_in_b + (size_t)l * 3 * DIM;
        const float* sow = sa_ow + (size_t)l * DIM * DIM;
        const float* sob = sa_ob + (size_t)l * DIM;
        const float* caw = ca_in_w + (size_t)l * 3 * DIM * DIM;
        const float* cab = ca_in_b + (size_t)l * 3 * DIM;
        const float* cow = ca_ow + (size_t)l * DIM * DIM;
        const float* cob = ca_ob + (size_t)l * DIM;

        // self-attention
        gemm_nt_mma<0><<<dim3(18, 64), 256, SMEM_MMA>>>(h, saw, sab, qkv, DIM, 3 * DIM);
        attn_scores<<<dim3(4, 8, 128), 256>>>(qkv, qkv + DIM, big, pad, 1);
        softmax_rows<<<BATCH * NHEAD * SEQ / 8, w32x8>>>(big);
        attn_pv<<<dim3(1, 8, 128), 256>>>(big, qkv + 2 * DIM, attn);
        gemm_nt_mma<0><<<dim3(6, 64), 256, SMEM_MMA>>>(attn, sow, sob, tmp, DIM, DIM);
        ln_kernel<<<NTOK, 256>>>(h, tmp, ln1g + l * DIM, ln1b + l * DIM);

        // cross-attention (memory = z_e)
        gemm_nt_mma<0><<<dim3(6, 64), 256, SMEM_MMA>>>(h, caw, cab, qkv, DIM, 3 * DIM);
        gemm_nt_mma<0><<<dim3(12, 64), 256, SMEM_MMA>>>(ze, caw + (size_t)DIM * DIM, cab + DIM,
                                                        qkv + DIM, DIM, 3 * DIM);
        attn_scores<<<dim3(4, 8, 128), 256>>>(qkv, qkv + DIM, big, pad, 0);
        softmax_rows<<<BATCH * NHEAD * SEQ / 8, w32x8>>>(big);
        attn_pv<<<dim3(1, 8, 128), 256>>>(big, qkv + 2 * DIM, attn);
        gemm_nt_mma<0><<<dim3(6, 64), 256, SMEM_MMA>>>(attn, cow, cob, tmp, DIM, DIM);
        ln_kernel<<<NTOK, 256>>>(h, tmp, ln2g + l * DIM, ln2b + l * DIM);

        // feed-forward
        gemm_nt_mma<1><<<dim3(16, 64), 256, SMEM_MMA>>>(h, ffw1 + (size_t)l * FFD * DIM,
                                                        ffb1 + (size_t)l * FFD, ffb, DIM, FFD);
        gemm_nt_mma<0><<<dim3(6, 64), 256, SMEM_MMA>>>(ffb, ffw2 + (size_t)l * DIM * FFD,
                                                       ffb2 + (size_t)l * DIM, tmp, FFD, DIM);
        ln_kernel<<<NTOK, 256>>>(h, tmp, ln3g + l * DIM, ln3b + l * DIM);
    }

    // --- output projection ---
    gemm_nt_mma<0><<<dim3(6, 64), 256, SMEM_MMA>>>(h, outw, outb, out, DIM, DIM);
}